// round 6
// baseline (speedup 1.0000x reference)
#include <cuda_runtime.h>
#include <cstdint>

// VQ nearest-codebook search (out emitted as float32 — harness dtype):
//   inputs [16,64,64,64] NCHW fp32, codebook [1024,64] fp32
//   out[n] = argmin_k ||x_n - e_k||^2 == argmax_k ( x_n.e_k - 0.5||e_k||^2 )
//
// R6: codes paired in f32x2 lanes; x pre-duplicated in smem (once per block).
//   Inner loop per d: 4 LDS.128 + 16 FMA2, zero MOV/DUP.  M_TILE=64 rows,
//   K_TILE=128 codes, 256 threads (16 tr x 16 tc), thread = 4 rows x 8 codes.

#define NUM_CODES 1024
#define DIM       64
#define M_TILE    64
#define K_TILE    128
#define THREADS   256
#define N_ROWS    65536
#define HW        4096

__device__ float g_nh[NUM_CODES];          // -0.5*||e_k||^2 (natural pair order)
__device__ float g_cbT[DIM][NUM_CODES];    // transposed codebook

#define FMA2(acc, a, b) \
    asm("fma.rn.f32x2 %0, %1, %2, %0;" : "+l"(acc) : "l"(a), "l"(b))

// ---------------------------------------------------------------------------
// Prep: tiled transpose (coalesced both sides) + norms. grid 16 x 256.
// ---------------------------------------------------------------------------
__global__ void vq_prep_kernel(const float* __restrict__ cb) {
    __shared__ float s[64][65];            // 64 codes x 64 dims, padded
    const int tid = threadIdx.x;
    const int k0  = blockIdx.x * 64;
#pragma unroll
    for (int i = 0; i < 4; ++i) {          // 1024 float4, coalesced reads
        int idx = i * THREADS + tid;
        int row = idx >> 4, c4 = idx & 15;
        float4 v = ((const float4*)(cb + (size_t)(k0 + row) * DIM))[c4];
        s[row][c4 * 4 + 0] = v.x;  s[row][c4 * 4 + 1] = v.y;
        s[row][c4 * 4 + 2] = v.z;  s[row][c4 * 4 + 3] = v.w;
    }
    __syncthreads();
    if (tid < 64) {                        // norms
        float acc = 0.f;
#pragma unroll
        for (int d = 0; d < DIM; ++d) acc = fmaf(s[tid][d], s[tid][d], acc);
        g_nh[k0 + tid] = -0.5f * acc;
    }
#pragma unroll
    for (int i = 0; i < 16; ++i) {         // coalesced writes
        int idx = i * THREADS + tid;
        int d = idx >> 6, j = idx & 63;
        g_cbT[d][k0 + j] = s[j][d];
    }
}

// ---------------------------------------------------------------------------
// Main search
// ---------------------------------------------------------------------------
struct Cand { float v; int i; };

__global__ __launch_bounds__(THREADS)
void vq_search_kernel(const float* __restrict__ in,
                      float* __restrict__ out) {
    __shared__ __align__(16) float xD[DIM][2 * M_TILE];  // 32 KB, rows dup'd
    __shared__ __align__(16) float eT[DIM][K_TILE];      // 32 KB

    const int tid = threadIdx.x;
    const int tr  = tid >> 4;              // 0..15 -> rows tr*4 .. tr*4+3
    const int tc  = tid & 15;              // 0..15 -> codes tc*8 .. tc*8+7
    const int r0  = tr * 4;
    const int c0  = tc * 8;

    // ---- x tile: 64 d x 64 consecutive rows, written duplicated ----
    const int rowBase = blockIdx.x * M_TILE;
    const int b   = rowBase >> 12;
    const int hw0 = rowBase & (HW - 1);
    const float* xin = in + ((size_t)b * DIM * HW) + hw0;
#pragma unroll
    for (int i = 0; i < 4; ++i) {          // 1024 float4 source, 4/thread
        int idx = i * THREADS + tid;
        int d = idx >> 4, m4 = idx & 15;
        float4 v = ((const float4*)(xin + (size_t)d * HW))[m4];
        float4 lo = make_float4(v.x, v.x, v.y, v.y);
        float4 hi = make_float4(v.z, v.z, v.w, v.w);
        ((float4*)&xD[d][0])[2 * m4 + 0] = lo;
        ((float4*)&xD[d][0])[2 * m4 + 1] = hi;
    }

    float best[4];
    int   bidx[4];
#pragma unroll
    for (int r = 0; r < 4; ++r) { best[r] = -3.402823466e38f; bidx[r] = 0; }

    for (int t = 0; t < NUM_CODES / K_TILE; ++t) {      // 8 tiles
        const int cBase = t * K_TILE;
        __syncthreads();                   // prev iter done reading eT
#pragma unroll
        for (int i = 0; i < 8; ++i) {      // e tile: 2048 float4, 8/thread
            int idx = i * THREADS + tid;
            int d = idx >> 5, j4 = idx & 31;
            ((float4*)&eT[d][0])[j4] = ((const float4*)&g_cbT[d][cBase])[j4];
        }
        __syncthreads();

        // accumulators init = -0.5||e||^2 pairs (no duplication needed)
        const ulonglong2 hA = *(const ulonglong2*)&g_nh[cBase + c0];
        const ulonglong2 hB = *(const ulonglong2*)&g_nh[cBase + c0 + 4];
        unsigned long long acc[4][4];
#pragma unroll
        for (int r = 0; r < 4; ++r) {
            acc[r][0] = hA.x; acc[r][1] = hA.y;
            acc[r][2] = hB.x; acc[r][3] = hB.y;
        }

#pragma unroll 16
        for (int d = 0; d < DIM; ++d) {
            const ulonglong2 xa = *(const ulonglong2*)&xD[d][2 * r0];     // rows r0,r0+1 (dup)
            const ulonglong2 xb = *(const ulonglong2*)&xD[d][2 * r0 + 4]; // rows r0+2,r0+3
            const ulonglong2 ea = *(const ulonglong2*)&eT[d][c0];         // code pairs 0,1
            const ulonglong2 eb = *(const ulonglong2*)&eT[d][c0 + 4];     // code pairs 2,3
            FMA2(acc[0][0], xa.x, ea.x); FMA2(acc[0][1], xa.x, ea.y);
            FMA2(acc[0][2], xa.x, eb.x); FMA2(acc[0][3], xa.x, eb.y);
            FMA2(acc[1][0], xa.y, ea.x); FMA2(acc[1][1], xa.y, ea.y);
            FMA2(acc[1][2], xa.y, eb.x); FMA2(acc[1][3], xa.y, eb.y);
            FMA2(acc[2][0], xb.x, ea.x); FMA2(acc[2][1], xb.x, ea.y);
            FMA2(acc[2][2], xb.x, eb.x); FMA2(acc[2][3], xb.x, eb.y);
            FMA2(acc[3][0], xb.y, ea.x); FMA2(acc[3][1], xb.y, ea.y);
            FMA2(acc[3][2], xb.y, eb.x); FMA2(acc[3][3], xb.y, eb.y);
        }

        // epilogue: codes visited ascending (p asc, lo lane before hi) ->
        // strict > keeps smallest index on ties, matching argmin.
#pragma unroll
        for (int p = 0; p < 4; ++p) {
            const int codeLo = cBase + c0 + 2 * p;
#pragma unroll
            for (int r = 0; r < 4; ++r) {
                unsigned long long a = acc[r][p];
                float vlo = __uint_as_float((unsigned)a);
                float vhi = __uint_as_float((unsigned)(a >> 32));
                if (vlo > best[r]) { best[r] = vlo; bidx[r] = codeLo; }
                if (vhi > best[r]) { best[r] = vhi; bidx[r] = codeLo + 1; }
            }
        }
    }

    // ---- cross-thread reduction over the 16 thread-cols ----
    __syncthreads();                       // everyone done with xD
    Cand* red = (Cand*)&xD[0][0];          // [M_TILE][16], 8 KB
#pragma unroll
    for (int r = 0; r < 4; ++r)
        red[(r0 + r) * 16 + tc] = Cand{best[r], bidx[r]};
    __syncthreads();

    if (tid < M_TILE) {
        Cand bc = red[tid * 16 + 0];
#pragma unroll
        for (int j = 1; j < 16; ++j) {
            Cand c = red[tid * 16 + j];
            if (c.v > bc.v || (c.v == bc.v && c.i < bc.i)) bc = c;
        }
        out[rowBase + tid] = (float)bc.i;
    }
}

// ---------------------------------------------------------------------------
// Harness entry
// ---------------------------------------------------------------------------
extern "C" void kernel_launch(void* const* d_in, const int* in_sizes, int n_in,
                              void* d_out, int out_size) {
    const float* inp = (const float*)d_in[0];
    const float* cb  = (const float*)d_in[1];
    if (in_sizes[0] == NUM_CODES * DIM && in_sizes[1] != NUM_CODES * DIM) {
        const float* tmp = inp; inp = cb; cb = tmp;
    }
    float* out = (float*)d_out;

    vq_prep_kernel<<<NUM_CODES / 64, THREADS>>>(cb);
    vq_search_kernel<<<N_ROWS / M_TILE, THREADS>>>(inp, out);
}

// round 7
// speedup vs baseline: 1.6557x; 1.6557x over previous
#include <cuda_runtime.h>
#include <cstdint>

// VQ nearest-codebook search (out emitted as float32 — harness dtype):
//   inputs [16,64,64,64] NCHW fp32, codebook [1024,64] fp32
//   out[n] = argmin_k ||x_n - e_k||^2 == argmax_k ( x_n.e_k - 0.5||e_k||^2 )
//
// R7: codes paired in f32x2 (no e-dup), x pre-duplicated in smem (no movs),
//   e reads stride-16B conflict-free (two 4-code blocks per thread),
//   thread = 8 rows x 8 codes, 128 threads, M_TILE=64, K_TILE=128,
//   smem 64KB -> 3 CTA/SM, grid 1024 -> ~1% tail.

#define NUM_CODES 1024
#define DIM       64
#define M_TILE    64
#define K_TILE    128
#define THREADS   128
#define N_ROWS    65536
#define HW        4096

__device__ float g_nh[NUM_CODES];          // -0.5*||e_k||^2
__device__ float g_cbT[DIM][NUM_CODES];    // transposed codebook

#define FMA2(acc, a, b) \
    asm("fma.rn.f32x2 %0, %1, %2, %0;" : "+l"(acc) : "l"(a), "l"(b))

// ---------------------------------------------------------------------------
// Prep: tiled transpose (coalesced both sides) + norms. grid 16 x 256.
// ---------------------------------------------------------------------------
__global__ void vq_prep_kernel(const float* __restrict__ cb) {
    __shared__ float s[64][65];
    const int tid = threadIdx.x;
    const int k0  = blockIdx.x * 64;
#pragma unroll
    for (int i = 0; i < 4; ++i) {
        int idx = i * 256 + tid;
        int row = idx >> 4, c4 = idx & 15;
        float4 v = ((const float4*)(cb + (size_t)(k0 + row) * DIM))[c4];
        s[row][c4 * 4 + 0] = v.x;  s[row][c4 * 4 + 1] = v.y;
        s[row][c4 * 4 + 2] = v.z;  s[row][c4 * 4 + 3] = v.w;
    }
    __syncthreads();
    if (tid < 64) {
        float acc = 0.f;
#pragma unroll
        for (int d = 0; d < DIM; ++d) acc = fmaf(s[tid][d], s[tid][d], acc);
        g_nh[k0 + tid] = -0.5f * acc;
    }
#pragma unroll
    for (int i = 0; i < 16; ++i) {
        int idx = i * 256 + tid;
        int d = idx >> 6, j = idx & 63;
        g_cbT[d][k0 + j] = s[j][d];
    }
}

// ---------------------------------------------------------------------------
// Main search
// ---------------------------------------------------------------------------
struct Cand { float v; int i; };

__global__ __launch_bounds__(THREADS, 3)
void vq_search_kernel(const float* __restrict__ in,
                      float* __restrict__ out) {
    __shared__ __align__(16) float xD[DIM][2 * M_TILE];  // 32 KB, rows dup'd
    __shared__ __align__(16) float eT[DIM][K_TILE];      // 32 KB

    const int tid = threadIdx.x;
    const int tr  = tid >> 4;              // 0..7  -> rows tr*8 .. tr*8+7
    const int tc  = tid & 15;              // 0..15 -> codes {4tc..4tc+3} u {64+4tc..}
    const int r0  = tr * 8;

    // ---- x tile: 64 d x 64 consecutive rows, written duplicated ----
    const int rowBase = blockIdx.x * M_TILE;
    const int b   = rowBase >> 12;
    const int hw0 = rowBase & (HW - 1);
    const float* xin = in + ((size_t)b * DIM * HW) + hw0;
#pragma unroll
    for (int i = 0; i < 8; ++i) {          // 1024 source float4, 8/thread
        int idx = i * THREADS + tid;
        int d = idx >> 4, m4 = idx & 15;   // 16 float4 per d-row (64 rows)
        float4 v = ((const float4*)(xin + (size_t)d * HW))[m4];
        ((float4*)&xD[d][0])[2 * m4 + 0] = make_float4(v.x, v.x, v.y, v.y);
        ((float4*)&xD[d][0])[2 * m4 + 1] = make_float4(v.z, v.z, v.w, v.w);
    }

    float best[8];
    int   bidx[8];
#pragma unroll
    for (int r = 0; r < 8; ++r) { best[r] = -3.402823466e38f; bidx[r] = 0; }

    for (int t = 0; t < NUM_CODES / K_TILE; ++t) {      // 8 tiles
        const int cBase = t * K_TILE;
        __syncthreads();                   // prev iter done reading eT
#pragma unroll
        for (int i = 0; i < 16; ++i) {     // e tile: 2048 float4, 16/thread
            int idx = i * THREADS + tid;
            int d = idx >> 5, j4 = idx & 31;
            ((float4*)&eT[d][0])[j4] = ((const float4*)&g_cbT[d][cBase])[j4];
        }
        __syncthreads();

        // acc init = -0.5||e||^2, natural pairs (no duplication)
        const ulonglong2 hA = *(const ulonglong2*)&g_nh[cBase + 4 * tc];
        const ulonglong2 hB = *(const ulonglong2*)&g_nh[cBase + 64 + 4 * tc];
        unsigned long long acc[8][4];
#pragma unroll
        for (int r = 0; r < 8; ++r) {
            acc[r][0] = hA.x; acc[r][1] = hA.y;
            acc[r][2] = hB.x; acc[r][3] = hB.y;
        }

#pragma unroll 8
        for (int d = 0; d < DIM; ++d) {
            // x: 8 dup'd rows = 64B, broadcast within warp (2 tr values)
            const ulonglong2 xa = *(const ulonglong2*)&xD[d][2 * r0];
            const ulonglong2 xb = *(const ulonglong2*)&xD[d][2 * r0 + 4];
            const ulonglong2 xc = *(const ulonglong2*)&xD[d][2 * r0 + 8];
            const ulonglong2 xd = *(const ulonglong2*)&xD[d][2 * r0 + 12];
            // e: stride-16B across tc -> conflict-free
            const ulonglong2 ea = *(const ulonglong2*)&eT[d][4 * tc];       // codes 4tc..4tc+3
            const ulonglong2 eb = *(const ulonglong2*)&eT[d][64 + 4 * tc];  // +64
            FMA2(acc[0][0], xa.x, ea.x); FMA2(acc[0][1], xa.x, ea.y);
            FMA2(acc[0][2], xa.x, eb.x); FMA2(acc[0][3], xa.x, eb.y);
            FMA2(acc[1][0], xa.y, ea.x); FMA2(acc[1][1], xa.y, ea.y);
            FMA2(acc[1][2], xa.y, eb.x); FMA2(acc[1][3], xa.y, eb.y);
            FMA2(acc[2][0], xb.x, ea.x); FMA2(acc[2][1], xb.x, ea.y);
            FMA2(acc[2][2], xb.x, eb.x); FMA2(acc[2][3], xb.x, eb.y);
            FMA2(acc[3][0], xb.y, ea.x); FMA2(acc[3][1], xb.y, ea.y);
            FMA2(acc[3][2], xb.y, eb.x); FMA2(acc[3][3], xb.y, eb.y);
            FMA2(acc[4][0], xc.x, ea.x); FMA2(acc[4][1], xc.x, ea.y);
            FMA2(acc[4][2], xc.x, eb.x); FMA2(acc[4][3], xc.x, eb.y);
            FMA2(acc[5][0], xc.y, ea.x); FMA2(acc[5][1], xc.y, ea.y);
            FMA2(acc[5][2], xc.y, eb.x); FMA2(acc[5][3], xc.y, eb.y);
            FMA2(acc[6][0], xd.x, ea.x); FMA2(acc[6][1], xd.x, ea.y);
            FMA2(acc[6][2], xd.x, eb.x); FMA2(acc[6][3], xd.x, eb.y);
            FMA2(acc[7][0], xd.y, ea.x); FMA2(acc[7][1], xd.y, ea.y);
            FMA2(acc[7][2], xd.y, eb.x); FMA2(acc[7][3], xd.y, eb.y);
        }

        // epilogue: within thread, codes ascending (p asc, lo before hi);
        // strict > keeps smallest index on ties == argmin first-min rule.
#pragma unroll
        for (int p = 0; p < 4; ++p) {
            const int codeLo = cBase + ((p < 2) ? (4 * tc + 2 * p)
                                                : (64 + 4 * tc + 2 * (p - 2)));
#pragma unroll
            for (int r = 0; r < 8; ++r) {
                unsigned long long a = acc[r][p];
                float vlo = __uint_as_float((unsigned)a);
                float vhi = __uint_as_float((unsigned)(a >> 32));
                if (vlo > best[r]) { best[r] = vlo; bidx[r] = codeLo; }
                if (vhi > best[r]) { best[r] = vhi; bidx[r] = codeLo + 1; }
            }
        }
    }

    // ---- cross-thread reduction over the 16 thread-cols ----
    __syncthreads();                       // everyone done with xD
    Cand* red = (Cand*)&xD[0][0];          // [M_TILE][16], 8 KB
#pragma unroll
    for (int r = 0; r < 8; ++r)
        red[(r0 + r) * 16 + tc] = Cand{best[r], bidx[r]};
    __syncthreads();

    if (tid < M_TILE) {
        Cand bc = red[tid * 16 + 0];
#pragma unroll
        for (int j = 1; j < 16; ++j) {
            Cand c = red[tid * 16 + j];
            if (c.v > bc.v || (c.v == bc.v && c.i < bc.i)) bc = c;
        }
        out[rowBase + tid] = (float)bc.i;
    }
}

// ---------------------------------------------------------------------------
// Harness entry
// ---------------------------------------------------------------------------
extern "C" void kernel_launch(void* const* d_in, const int* in_sizes, int n_in,
                              void* d_out, int out_size) {
    const float* inp = (const float*)d_in[0];
    const float* cb  = (const float*)d_in[1];
    if (in_sizes[0] == NUM_CODES * DIM && in_sizes[1] != NUM_CODES * DIM) {
        const float* tmp = inp; inp = cb; cb = tmp;
    }
    float* out = (float*)d_out;

    vq_prep_kernel<<<NUM_CODES / 64, 256>>>(cb);
    vq_search_kernel<<<N_ROWS / M_TILE, THREADS>>>(inp, out);
}

// round 9
// speedup vs baseline: 2.0492x; 1.2377x over previous
#include <cuda_runtime.h>
#include <cuda_bf16.h>
#include <cstdint>

// VQ nearest-codebook search via warp-level mma.sync (HMMA, baseline PTX —
// the harness targets compute_103, so no tcgen05/'a' features).
//   inputs [16,64,64,64] NCHW fp32, codebook [1024,64] fp32
//   out[n] (as float32) = argmin_k ||x_n - e_k||^2
//                       = argmax_k ( x_n.e_k - 0.5||e_k||^2 )
// bf16 triple-split x = b0+b1+b2; 6 accumulating bf16 MMA passes
// (00,10,20,01,11,02) into fp32 accumulators -> fp32-class accuracy.

#define NUM_CODES 1024
#define DIM       64
#define M_TILE    128
#define N_CHUNK   128
#define CHUNKS    8
#define THREADS   256
#define N_ROWS    65536
#define HW        4096
#define TILEB     16384            // one [128 codes/rows][64 bf16] tile

// smem layout (relative to 1024-aligned base)
#define SM_H      0                // 1024 floats (-0.5||e||^2)
#define SM_A      4096             // 3 comps x 16 KB
#define SM_B      (SM_A + 3 * TILEB)   // 2 bufs x 3 comps x 16 KB
#define SM_TOTAL  (SM_B + 6 * TILEB)   // 151552
#define SM_ALLOC  (SM_TOTAL + 1024)

__device__ float g_h[NUM_CODES];                       // -0.5*||e_k||^2
__device__ __align__(16) unsigned char g_bsplit[3 * CHUNKS * TILEB];

#define SW128(o) ((o) ^ (((o) >> 3) & 0x70))

__device__ __forceinline__ uint32_t smem_u32(const void* p) {
    uint32_t a;
    asm("{ .reg .u64 t; cvta.to.shared.u64 t, %1; cvt.u32.u64 %0, t; }"
        : "=r"(a) : "l"(p));
    return a;
}

#define LDSM_X4(r, a) \
    asm volatile("ldmatrix.sync.aligned.m8n8.x4.shared.b16 {%0,%1,%2,%3}, [%4];" \
        : "=r"((r)[0]), "=r"((r)[1]), "=r"((r)[2]), "=r"((r)[3]) : "r"(a))
#define LDSM_X2(r, a) \
    asm volatile("ldmatrix.sync.aligned.m8n8.x2.shared.b16 {%0,%1}, [%2];" \
        : "=r"((r)[0]), "=r"((r)[1]) : "r"(a))
#define MMA(c, A, B) \
    asm volatile("mma.sync.aligned.m16n8k16.row.col.f32.bf16.bf16.f32 " \
        "{%0,%1,%2,%3}, {%4,%5,%6,%7}, {%8,%9}, {%0,%1,%2,%3};" \
        : "+f"((c)[0]), "+f"((c)[1]), "+f"((c)[2]), "+f"((c)[3]) \
        : "r"((A)[0]), "r"((A)[1]), "r"((A)[2]), "r"((A)[3]), \
          "r"((B)[0]), "r"((B)[1]))
#define CP16(dst, src) \
    asm volatile("cp.async.cg.shared.global [%0], [%1], 16;" :: "r"(dst), "l"(src))
#define CP_COMMIT() asm volatile("cp.async.commit_group;" ::: "memory")
#define CP_WAIT(n)  asm volatile("cp.async.wait_group %0;" :: "n"(n) : "memory")

__device__ __forceinline__ uint32_t pack_bf16(__nv_bfloat16 lo, __nv_bfloat16 hi) {
    return ((uint32_t)__bfloat16_as_ushort(hi) << 16) | __bfloat16_as_ushort(lo);
}
__device__ __forceinline__ void split3(float x, __nv_bfloat16& c0,
                                       __nv_bfloat16& c1, __nv_bfloat16& c2) {
    c0 = __float2bfloat16(x);
    float r0 = x - __bfloat162float(c0);
    c1 = __float2bfloat16(r0);
    float r1 = r0 - __bfloat162float(c1);
    c2 = __float2bfloat16(r1);
}

// ---------------------------------------------------------------------------
// Prep: split codebook into 3 bf16 comps, pre-swizzled tiles; -0.5 norms.
// ---------------------------------------------------------------------------
__global__ void vq_prep(const float* __restrict__ cb) {
    int j = blockIdx.x * blockDim.x + threadIdx.x;   // code 0..1023
    if (j >= NUM_CODES) return;
    int chunk = j >> 7, jr = j & 127;
    float nrm = 0.f;
    for (int dp = 0; dp < 32; ++dp) {
        float x0 = cb[(size_t)j * DIM + 2 * dp];
        float x1 = cb[(size_t)j * DIM + 2 * dp + 1];
        nrm = fmaf(x0, x0, nrm);
        nrm = fmaf(x1, x1, nrm);
        __nv_bfloat16 a0, a1, a2, b0, b1, b2;
        split3(x0, a0, a1, a2);
        split3(x1, b0, b1, b2);
        uint32_t sw = SW128((uint32_t)(jr * 128 + dp * 4));
        *(uint32_t*)&g_bsplit[(0 * CHUNKS + chunk) * TILEB + sw] = pack_bf16(a0, b0);
        *(uint32_t*)&g_bsplit[(1 * CHUNKS + chunk) * TILEB + sw] = pack_bf16(a1, b1);
        *(uint32_t*)&g_bsplit[(2 * CHUNKS + chunk) * TILEB + sw] = pack_bf16(a2, b2);
    }
    g_h[j] = -0.5f * nrm;
}

// ---------------------------------------------------------------------------
// Main kernel
// ---------------------------------------------------------------------------
__device__ __forceinline__ void cp_chunk(uint32_t sb, int c, int bb, int tid) {
#pragma unroll
    for (int t = 0; t < 3; ++t) {
#pragma unroll
        for (int i = 0; i < 4; ++i) {
            int idx = i * THREADS + tid;
            uint32_t dst = sb + SM_B + (bb * 3 + t) * TILEB + idx * 16;
            const unsigned char* src = &g_bsplit[(t * CHUNKS + c) * TILEB + idx * 16];
            CP16(dst, src);
        }
    }
}

__global__ __launch_bounds__(THREADS)
void vq_mma_kernel(const float* __restrict__ in, float* __restrict__ out) {
    extern __shared__ char smraw[];
    const uint32_t sbr = smem_u32(smraw);
    const uint32_t sb  = (sbr + 1023u) & ~1023u;    // 1K-align for swizzle
    char* sm = smraw + (sb - sbr);

    const int tid  = threadIdx.x;
    const int wid  = tid >> 5;
    const int lane = tid & 31;

    // -0.5||e||^2 -> smem
    float* sh = (float*)(sm + SM_H);
    for (int i = tid; i < NUM_CODES; i += THREADS) sh[i] = g_h[i];

    // build A: 128 rows x 64 ch, triple-split bf16, swizzled
    const int rowBase = blockIdx.x * M_TILE;
    const int b   = rowBase >> 12;
    const int hw0 = rowBase & (HW - 1);
    const float* xin = in + ((size_t)b * DIM * HW) + hw0;
#pragma unroll
    for (int i = 0; i < 16; ++i) {
        int idx = i * THREADS + tid;
        int r = idx & 127, dp = idx >> 7;
        float x0 = xin[(size_t)(2 * dp) * HW + r];
        float x1 = xin[(size_t)(2 * dp + 1) * HW + r];
        __nv_bfloat16 a0, a1, a2, b0, b1, b2;
        split3(x0, a0, a1, a2);
        split3(x1, b0, b1, b2);
        uint32_t sw = SW128((uint32_t)(r * 128 + dp * 4));
        *(uint32_t*)(sm + SM_A + 0 * TILEB + sw) = pack_bf16(a0, b0);
        *(uint32_t*)(sm + SM_A + 1 * TILEB + sw) = pack_bf16(a1, b1);
        *(uint32_t*)(sm + SM_A + 2 * TILEB + sw) = pack_bf16(a2, b2);
    }

    // prefetch B chunk 0
    cp_chunk(sb, 0, 0, tid);
    CP_COMMIT();

    __syncthreads();      // A + h ready

    // A fragments in registers: warp w = rows w*16..w*16+15.
    // ldmatrix.x4: lane l -> row (l&15), col-halves by l>>4.
    uint32_t Af[3][4][4];
    {
        const int arow = wid * 16 + (lane & 15);
        const uint32_t colb = (uint32_t)((lane >> 4) * 16);
#pragma unroll
        for (int t = 0; t < 3; ++t)
#pragma unroll
            for (int ks = 0; ks < 4; ++ks) {
                uint32_t off = (uint32_t)(arow * 128)
                             + ((colb + ks * 32) ^ ((uint32_t)(arow & 7) << 4));
                LDSM_X4(Af[t][ks], sb + SM_A + t * TILEB + off);
            }
    }

    // B ldmatrix lane geometry (lanes 0-15 meaningful, others mirrored)
    const int bl     = lane & 15;
    const int brow7  = bl & 7;                 // code row % 8
    const uint32_t bmsel = (uint32_t)((bl >> 3) * 16);  // matrix1 = k+8
    const int colOff = 2 * (lane & 3);

    float best0 = -3.402823466e38f, best1 = -3.402823466e38f;
    int   bi0 = 0, bi1 = 0;

    for (int c = 0; c < CHUNKS; ++c) {
        const int bb = c & 1;
        if (c) __syncthreads();                // all done reading buf bb
        if (c + 1 < CHUNKS) {
            cp_chunk(sb, c + 1, bb ^ 1, tid);
            CP_COMMIT();
            CP_WAIT(1);                        // chunk c arrived
        } else {
            CP_WAIT(0);
        }
        __syncthreads();                       // chunk c visible to all

        // C init = -0.5||e||^2 (rows lane>>2 and +8 share columns)
        float C[16][4];
#pragma unroll
        for (int n8 = 0; n8 < 16; ++n8) {
            float2 h2 = *(const float2*)&sh[c * N_CHUNK + n8 * 8 + colOff];
            C[n8][0] = h2.x; C[n8][1] = h2.y;
            C[n8][2] = h2.x; C[n8][3] = h2.y;
        }

        const uint32_t bbase = sb + SM_B + bb * 3 * TILEB + brow7 * 128;
#pragma unroll
        for (int ks = 0; ks < 4; ++ks) {
            const uint32_t kc = ((uint32_t)(ks * 32) + bmsel)
                              ^ ((uint32_t)brow7 << 4);
#pragma unroll
            for (int n8 = 0; n8 < 16; ++n8) {
                const uint32_t a = bbase + n8 * 1024 + kc;
                uint32_t b0[2], b1[2], b2[2];
                LDSM_X2(b0, a);
                LDSM_X2(b1, a + TILEB);
                LDSM_X2(b2, a + 2 * TILEB);
                MMA(C[n8], Af[0][ks], b0);     // x0*e0
                MMA(C[n8], Af[1][ks], b0);     // x1*e0
                MMA(C[n8], Af[2][ks], b0);     // x2*e0
                MMA(C[n8], Af[0][ks], b1);     // x0*e1
                MMA(C[n8], Af[1][ks], b1);     // x1*e1
                MMA(C[n8], Af[0][ks], b2);     // x0*e2
            }
        }

        // epilogue: argmax over this chunk (codes ascending -> first-min tie)
#pragma unroll
        for (int n8 = 0; n8 < 16; ++n8) {
            const int code = c * N_CHUNK + n8 * 8 + colOff;
            if (C[n8][0] > best0) { best0 = C[n8][0]; bi0 = code; }
            if (C[n8][1] > best0) { best0 = C[n8][1]; bi0 = code + 1; }
            if (C[n8][2] > best1) { best1 = C[n8][2]; bi1 = code; }
            if (C[n8][3] > best1) { best1 = C[n8][3]; bi1 = code + 1; }
        }
    }

    // cross-lane reduce among the 4 lanes sharing each row
#pragma unroll
    for (int off = 1; off <= 2; off <<= 1) {
        float v0 = __shfl_xor_sync(0xFFFFFFFFu, best0, off);
        int   i0 = __shfl_xor_sync(0xFFFFFFFFu, bi0,   off);
        if (v0 > best0 || (v0 == best0 && i0 < bi0)) { best0 = v0; bi0 = i0; }
        float v1 = __shfl_xor_sync(0xFFFFFFFFu, best1, off);
        int   i1 = __shfl_xor_sync(0xFFFFFFFFu, bi1,   off);
        if (v1 > best1 || (v1 == best1 && i1 < bi1)) { best1 = v1; bi1 = i1; }
    }
    if ((lane & 3) == 0) {
        const int r = lane >> 2;
        out[rowBase + wid * 16 + r]     = (float)bi0;
        out[rowBase + wid * 16 + r + 8] = (float)bi1;
    }
}

// ---------------------------------------------------------------------------
// Harness entry
// ---------------------------------------------------------------------------
extern "C" void kernel_launch(void* const* d_in, const int* in_sizes, int n_in,
                              void* d_out, int out_size) {
    const float* inp = (const float*)d_in[0];
    const float* cb  = (const float*)d_in[1];
    if (in_sizes[0] == NUM_CODES * DIM && in_sizes[1] != NUM_CODES * DIM) {
        const float* tmp = inp; inp = cb; cb = tmp;
    }
    float* out = (float*)d_out;

    cudaFuncSetAttribute(vq_mma_kernel,
                         cudaFuncAttributeMaxDynamicSharedMemorySize, SM_ALLOC);
    vq_prep<<<NUM_CODES / 256, 256>>>(cb);
    vq_mma_kernel<<<N_ROWS / M_TILE, THREADS, SM_ALLOC>>>(inp, out);
}